// round 6
// baseline (speedup 1.0000x reference)
#include <cuda_runtime.h>
#include <cuda_bf16.h>

// ---------------------------------------------------------------------------
// SpectralConv2d: B=8, Cin=Cout=32, S=256, REGION=64 (16 disjoint regions),
// MAX_M=16. Per (region r, batch b): n = f(error mean), pipeline:
//   E  = C16x64 * x_region * C16x64^T            (corner of 64-pt DHT)
//   X  = dht2_n(E[:n,:n])                        (small non-separable DHT)
//   Y  = dht2_n(w[:,:, :n,:n]);  Ye/Yo = 0.5*(Y +/- Y o flip)   (flattened flip)
//   Z[o,t] = sum_i X[i,t] Ye[i,o,t] + X[i,flip t] Yo[i,o,t]
//   blk = dht2_n(Z)/n^2, zero-padded to 16x16
//   out_region = C64x16 * blk * C64x16^T / 4096
// ---------------------------------------------------------------------------

__device__ float g_cas64[64];
__device__ float g_C[64 * 16];     // [p][u] = cas(2*pi*u*p/64)
__device__ float g_CT[16 * 64];    // [v][q] = cas(2*pi*v*q/64) (transposed copy)
__device__ float g_trig[16 * 64];  // [n-1][{cos,sin,cas,casneg} x 16]
__device__ float g_avg[128];       // [region*8 + b]
__device__ int   g_n[128];
__device__ int   g_used[16];
__device__ float g_Xc[128 * 32 * 256];    // [rb][cin][t]
__device__ float g_Ye[16 * 256 * 1024];   // [n-1][t][o*32+i]
__device__ float g_Yo[16 * 256 * 1024];
__device__ float g_Zm[128 * 32 * 256];    // [rb][cout][t]
__device__ float g_blk[128 * 32 * 256];   // [rb][cout][16*16], zero-padded

// ---------------------------------------------------------------------------
__global__ void k_init() {
    int tid = threadIdx.x;
    if (tid < 64) {
        double s, c;
        sincospi(2.0 * (double)tid / 64.0, &s, &c);
        g_cas64[tid] = (float)(c + s);
    }
    __syncthreads();
    for (int idx = tid; idx < 64 * 16; idx += 256) {
        int p = idx >> 4, u = idx & 15;
        g_C[idx] = g_cas64[(u * p) & 63];
    }
    for (int idx = tid; idx < 16 * 64; idx += 256) {
        int v = idx >> 6, q = idx & 63;
        g_CT[idx] = g_cas64[(v * q) & 63];
    }
    {
        int nm1 = tid >> 4, j = tid & 15;
        int n = nm1 + 1;
        if (j < n) {
            double s, c;
            sincospi(2.0 * (double)j / (double)n, &s, &c);
            g_trig[nm1 * 64 +  0 + j] = (float)c;
            g_trig[nm1 * 64 + 16 + j] = (float)s;
            g_trig[nm1 * 64 + 32 + j] = (float)(c + s);
            g_trig[nm1 * 64 + 48 + j] = (float)(c - s);
        }
    }
    if (tid < 16) g_used[tid] = 0;
}

// ---------------------------------------------------------------------------
__global__ void k_avg(const float* __restrict__ err) {
    __shared__ double sm[256];
    int rb = blockIdx.x;
    int r = rb >> 3, b = rb & 7;
    int s1 = (r >> 2) * 64, s2 = (r & 3) * 64;
    const float* base = err + (size_t)b * 65536 + s1 * 256 + s2;
    double sum = 0.0;
    for (int k = threadIdx.x; k < 4096; k += 256)
        sum += (double)base[(k >> 6) * 256 + (k & 63)];
    sm[threadIdx.x] = sum;
    __syncthreads();
    for (int st = 128; st > 0; st >>= 1) {
        if (threadIdx.x < st) sm[threadIdx.x] += sm[threadIdx.x + st];
        __syncthreads();
    }
    if (threadIdx.x == 0) g_avg[rb] = (float)(sm[0] * (1.0 / 4096.0));
}

__global__ void k_nsel() {
    int t = threadIdx.x;  // 128 threads
    int r = t >> 3;
    float mn = g_avg[r * 8], mx = mn;
    for (int k = 1; k < 8; k++) {
        float a = g_avg[r * 8 + k];
        mn = fminf(mn, a);
        mx = fmaxf(mx, a);
    }
    float d = mx - mn;
    float norm = ((double)d > 1e-8) ? (g_avg[t] - mn) / d : 0.0f;
    int n = (int)(norm * 15.0f) + 1;
    if (n > 16) n = 16;
    g_n[t] = n;
    g_used[n - 1] = 1;
}

// ---------------------------------------------------------------------------
// Corner projection (64x64 -> 16x16) fused with forward n x n dht2.
// Grid (ci=32, b=8, r=16), block 256.
__global__ void k_corner(const float* __restrict__ x) {
    __shared__ __align__(16) float xs[64 * 64];
    __shared__ __align__(16) float Cs[64 * 16];
    __shared__ float Ts[16 * 64];
    __shared__ float Es[256];
    __shared__ float As[256], Bs[256];
    __shared__ float tg[64];
    int ci = blockIdx.x, b = blockIdx.y, r = blockIdx.z;
    int tid = threadIdx.x;
    int s1 = (r >> 2) * 64, s2 = (r & 3) * 64;
    const float* base = x + (size_t)(b * 32 + ci) * 65536 + s1 * 256 + s2;
    for (int k = tid; k < 1024; k += 256) {
        int p = k >> 4, c4 = k & 15;
        ((float4*)xs)[p * 16 + c4] = ((const float4*)(base + p * 256))[c4];
    }
    for (int k = tid; k < 1024; k += 256) Cs[k] = g_C[k];
    int rb = r * 8 + b;
    int n = g_n[rb];
    if (tid < 64) tg[tid] = g_trig[(n - 1) * 64 + tid];
    __syncthreads();
    // stage 1: T[u][q] = sum_p cas64(u*p) * x[p][q]
    {
        int qt = tid & 63, ug = tid >> 6;
        float a0 = 0, a1 = 0, a2 = 0, a3 = 0;
#pragma unroll
        for (int p = 0; p < 64; p++) {
            float xv = xs[p * 64 + qt];
            float4 c = ((float4*)Cs)[p * 4 + ug];
            a0 += xv * c.x; a1 += xv * c.y; a2 += xv * c.z; a3 += xv * c.w;
        }
        int u0 = ug * 4;
        Ts[(u0 + 0) * 64 + qt] = a0;
        Ts[(u0 + 1) * 64 + qt] = a1;
        Ts[(u0 + 2) * 64 + qt] = a2;
        Ts[(u0 + 3) * 64 + qt] = a3;
    }
    __syncthreads();
    // stage 2: E[u][v] = sum_q T[u][q] * cas64(v*q)
    {
        int u = tid >> 4, v = tid & 15;
        float acc = 0;
#pragma unroll
        for (int q = 0; q < 64; q++) acc += Ts[u * 64 + q] * Cs[q * 16 + v];
        Es[tid] = acc;
    }
    __syncthreads();
    const float* cosn = tg, *sinn = tg + 16, *casn = tg + 32, *casng = tg + 48;
    int nn = n * n;
    // A[u,k2] = sum_v E[u][v] cas_n(k2 v);  B with cas_n(-k2 v)
    for (int idx = tid; idx < nn; idx += 256) {
        int u = idx / n, k2 = idx - u * n;
        float a = 0, bb = 0;
        int ph = 0;
        for (int v = 0; v < n; v++) {
            float e = Es[u * 16 + v];
            a  += e * casn[ph];
            bb += e * casng[ph];
            ph += k2; if (ph >= n) ph -= n;
        }
        As[idx] = a; Bs[idx] = bb;
    }
    __syncthreads();
    // X[k1,k2] = sum_u cos(k1 u) A[u,k2] + sin(k1 u) B[u,k2]
    float* xout = g_Xc + (size_t)(rb * 32 + ci) * 256;
    for (int idx = tid; idx < nn; idx += 256) {
        int k1 = idx / n, k2 = idx - k1 * n;
        float acc = 0;
        int ph = 0;
        for (int u = 0; u < n; u++) {
            acc += cosn[ph] * As[u * n + k2] + sinn[ph] * Bs[u * n + k2];
            ph += k1; if (ph >= n) ph -= n;
        }
        xout[idx] = acc;
    }
}

// ---------------------------------------------------------------------------
// Weight transform: for each used n, Y = dht2_n(w[i,o,:n,:n]) -> Ye/Yo tables.
// Grid (pair-chunk=128 of 8 pairs, nm1=16), block 256.
__global__ void k_wy(const float* __restrict__ w) {
    int nm1 = blockIdx.y;
    if (!g_used[nm1]) return;
    int n = nm1 + 1, nn = n * n;
    int p0 = blockIdx.x * 8;
    __shared__ __align__(16) float ws[8 * 256];
    __shared__ float As[8 * 256], Bs[8 * 256], Ys[8 * 256];
    __shared__ float tg[64];
    int tid = threadIdx.x;
    for (int k = tid; k < 8 * 64; k += 256)
        ((float4*)ws)[k] = ((const float4*)(w + (size_t)p0 * 256))[k];
    if (tid < 64) tg[tid] = g_trig[nm1 * 64 + tid];
    __syncthreads();
    const float* cosn = tg, *sinn = tg + 16, *casn = tg + 32, *casng = tg + 48;
    for (int idx = tid; idx < 8 * nn; idx += 256) {
        int pl = idx / nn, rem = idx - pl * nn;
        int u = rem / n, k2 = rem - u * n;
        float a = 0, bb = 0;
        int ph = 0;
        for (int v = 0; v < n; v++) {
            float e = ws[pl * 256 + u * 16 + v];
            a  += e * casn[ph];
            bb += e * casng[ph];
            ph += k2; if (ph >= n) ph -= n;
        }
        As[pl * 256 + rem] = a; Bs[pl * 256 + rem] = bb;
    }
    __syncthreads();
    for (int idx = tid; idx < 8 * nn; idx += 256) {
        int pl = idx / nn, rem = idx - pl * nn;
        int k1 = rem / n, k2 = rem - k1 * n;
        float acc = 0;
        int ph = 0;
        for (int u = 0; u < n; u++) {
            acc += cosn[ph] * As[pl * 256 + u * n + k2]
                 + sinn[ph] * Bs[pl * 256 + u * n + k2];
            ph += k1; if (ph >= n) ph -= n;
        }
        Ys[pl * 256 + rem] = acc;
    }
    __syncthreads();
    for (int idx = tid; idx < 8 * nn; idx += 256) {
        int pl = idx / nn, t = idx - pl * nn;
        int tf = (t == 0) ? 0 : (nn - t);
        float y = Ys[pl * 256 + t], yf = Ys[pl * 256 + tf];
        int pair = p0 + pl;
        int i = pair >> 5, o = pair & 31;
        size_t addr = (size_t)(nm1 * 256 + t) * 1024 + o * 32 + i;
        g_Ye[addr] = 0.5f * (y + yf);
        g_Yo[addr] = 0.5f * (y - yf);
    }
}

// ---------------------------------------------------------------------------
// Channel mix: Z[o,t] = sum_i X[i,t] Ye + X[i,flip t] Yo. Grid 128 (rb).
__global__ void k_mix() {
    __shared__ float Xs[32 * 256];
    int rb = blockIdx.x;
    int n = g_n[rb], nn = n * n, nm1 = n - 1;
    int tid = threadIdx.x;
    for (int idx = tid; idx < 32 * nn; idx += 256) {
        int i = idx / nn, t = idx - i * nn;
        Xs[i * 256 + t] = g_Xc[(size_t)(rb * 32 + i) * 256 + t];
    }
    __syncthreads();
    int wrp = tid >> 5, o = tid & 31;
    const float* YeB = g_Ye + (size_t)nm1 * 256 * 1024;
    const float* YoB = g_Yo + (size_t)nm1 * 256 * 1024;
    for (int t = wrp; t < nn; t += 8) {
        int tf = (t == 0) ? 0 : (nn - t);
        const float4* ye4 = (const float4*)(YeB + (size_t)t * 1024 + o * 32);
        const float4* yo4 = (const float4*)(YoB + (size_t)t * 1024 + o * 32);
        float acc = 0;
#pragma unroll
        for (int i4 = 0; i4 < 8; i4++) {
            float4 ye = ye4[i4], yo = yo4[i4];
            int ib = i4 * 4;
            acc += Xs[(ib + 0) * 256 + t] * ye.x + Xs[(ib + 1) * 256 + t] * ye.y
                 + Xs[(ib + 2) * 256 + t] * ye.z + Xs[(ib + 3) * 256 + t] * ye.w;
            acc += Xs[(ib + 0) * 256 + tf] * yo.x + Xs[(ib + 1) * 256 + tf] * yo.y
                 + Xs[(ib + 2) * 256 + tf] * yo.z + Xs[(ib + 3) * 256 + tf] * yo.w;
        }
        g_Zm[(size_t)rb * 8192 + o * 256 + t] = acc;
    }
}

// ---------------------------------------------------------------------------
// blk = dht2_n(Z)/nn, zero-padded to 16x16. Grid 128 (rb).
__global__ void k_zht() {
    __shared__ float Zs[8 * 256], As[8 * 256], Bs[8 * 256];
    __shared__ float tg[64];
    int rb = blockIdx.x;
    int n = g_n[rb], nn = n * n;
    int tid = threadIdx.x;
    if (tid < 64) tg[tid] = g_trig[(n - 1) * 64 + tid];
    __syncthreads();
    const float* cosn = tg, *sinn = tg + 16, *casn = tg + 32, *casng = tg + 48;
    float inv = 1.0f / (float)nn;
    for (int oc = 0; oc < 32; oc += 8) {
        for (int idx = tid; idx < 8 * nn; idx += 256) {
            int pl = idx / nn, t = idx - pl * nn;
            Zs[pl * 256 + t] = g_Zm[(size_t)rb * 8192 + (oc + pl) * 256 + t];
        }
        __syncthreads();
        for (int idx = tid; idx < 8 * nn; idx += 256) {
            int pl = idx / nn, rem = idx - pl * nn;
            int u = rem / n, k2 = rem - u * n;
            float a = 0, bb = 0;
            int ph = 0;
            for (int v = 0; v < n; v++) {
                float e = Zs[pl * 256 + u * n + v];
                a  += e * casn[ph];
                bb += e * casng[ph];
                ph += k2; if (ph >= n) ph -= n;
            }
            As[pl * 256 + rem] = a; Bs[pl * 256 + rem] = bb;
        }
        __syncthreads();
        for (int idx = tid; idx < 8 * 256; idx += 256) {
            int pl = idx >> 8, j = idx & 255;
            int k1 = j >> 4, k2 = j & 15;
            float val = 0.0f;
            if (k1 < n && k2 < n) {
                float acc = 0;
                int ph = 0;
                for (int u = 0; u < n; u++) {
                    acc += cosn[ph] * As[pl * 256 + u * n + k2]
                         + sinn[ph] * Bs[pl * 256 + u * n + k2];
                    ph += k1; if (ph >= n) ph -= n;
                }
                val = acc * inv;
            }
            g_blk[(size_t)(rb * 32 + oc + pl) * 256 + j] = val;
        }
        __syncthreads();
    }
}

// ---------------------------------------------------------------------------
// Expansion: out_region = C64x16 * blk * C64x16^T / 4096. Grid (co,b,r).
__global__ void k_out(float* __restrict__ out) {
    __shared__ float Bs[256];
    __shared__ float Cs[64 * 16];   // [p][u]
    __shared__ float CT[16 * 64];   // [v][q]
    __shared__ float Ts[64 * 16];
    int co = blockIdx.x, b = blockIdx.y, r = blockIdx.z;
    int tid = threadIdx.x;
    int rb = r * 8 + b;
    Bs[tid] = g_blk[(size_t)(rb * 32 + co) * 256 + tid];
    for (int k = tid; k < 1024; k += 256) { Cs[k] = g_C[k]; CT[k] = g_CT[k]; }
    __syncthreads();
    // T[p][v] = sum_u cas64(p*u) blk[u][v]
    for (int idx = tid; idx < 1024; idx += 256) {
        int p = idx >> 4, v = idx & 15;
        float acc = 0;
#pragma unroll
        for (int u = 0; u < 16; u++) acc += Cs[p * 16 + u] * Bs[u * 16 + v];
        Ts[idx] = acc;
    }
    __syncthreads();
    int s1 = (r >> 2) * 64, s2 = (r & 3) * 64;
    float* ob = out + (size_t)(b * 32 + co) * 65536 + s1 * 256 + s2;
    const float inv = 1.0f / 4096.0f;
    // out[p][q] = sum_v T[p][v] cas64(q*v)
    for (int idx = tid; idx < 4096; idx += 256) {
        int p = idx >> 6, q = idx & 63;
        float acc = 0;
#pragma unroll
        for (int v = 0; v < 16; v++) acc += Ts[p * 16 + v] * CT[v * 64 + q];
        ob[p * 256 + q] = acc * inv;
    }
}

// ---------------------------------------------------------------------------
extern "C" void kernel_launch(void* const* d_in, const int* in_sizes, int n_in,
                              void* d_out, int out_size) {
    const float* x   = (const float*)d_in[0];
    const float* err = (const float*)d_in[1];
    const float* w   = (const float*)d_in[2];
    float* out = (float*)d_out;
    k_init<<<1, 256>>>();
    k_avg<<<128, 256>>>(err);
    k_nsel<<<1, 128>>>();
    k_corner<<<dim3(32, 8, 16), 256>>>(x);
    k_wy<<<dim3(128, 16), 256>>>(w);
    k_mix<<<128, 256>>>();
    k_zht<<<128, 256>>>();
    k_out<<<dim3(32, 8, 16), 256>>>(out);
}